// round 8
// baseline (speedup 1.0000x reference)
#include <cuda_runtime.h>
#include <math.h>

typedef unsigned long long ull;

// ---------------- problem constants ----------------
#define NT       256     // 8 warps per CTA
#define BT       8       // batch items per CTA -> 256 CTAs, 2 resident per SM
#define T_STEPS  128
#define STATE    115
#define ACT      39
#define CIN      154
#define COUT     116

// buffer strides (floats); all give conflict-free float4 for 8 b-lanes
#define SBA 132          // BUFA (holds up to 128-wide)
#define SBB 68           // BUFB (holds up to 64-wide)
#define SXS 116          // state buffer (115 + 1 pad)
#define AOFF 24          // action block lives at BUFB cols 24..63

// ---------------- shared memory layout (float offsets) ----------------
#define OW0   0          // padded [156][16]: rows 0..114 x, 115 zero, 116..154 act, 155 zero
#define OW1   2496       // 16*32
#define OW2   3008       // 32*64
#define OW3   5056       // 64*128
#define OW4   13248      // 128*64
#define OW5   21440      // 64*32
#define OW6   23488      // 32*16
#define OW7   24000      // 16*8
#define OW8   24128      // padded [8][120]
#define OWR   25088      // 348
#define OB0   25436
#define OB1   25452
#define OB2   25484
#define OB3   25548
#define OB4   25676
#define OB5   25740
#define OB6   25772
#define OB7   25788
#define OB8   25796      // 120 padded
#define OBR   25916      // 4
#define OBUFA 25920      // 8*132 = 1056 (cols 32..47 double as L0 scratch)
#define OBUFB 26976      // 8*68  = 544  (cols 24..63 double as action stage)
#define OXS   27520      // 8*116 = 928
#define SMEM_FLOATS 28448
#define SMEM_BYTES  (SMEM_FLOATS * 4)   // 113792 B -> 2 CTAs/SM

struct Params {
    const float* u;
    const float* W[9];
    const float* b[9];
    const float* Wr;
    const float* br;
    float* out;
};

// ---- packed f32x2 helpers ----
__device__ __forceinline__ ull pk2(float x, float y) {
    ull r; asm("mov.b64 %0, {%1, %2};" : "=l"(r) : "f"(x), "f"(y)); return r;
}
__device__ __forceinline__ void upk2(ull v, float& x, float& y) {
    asm("mov.b64 {%0, %1}, %2;" : "=f"(x), "=f"(y) : "l"(v));
}
__device__ __forceinline__ ull fma2(ull a, ull b, ull c) {
    ull d; asm("fma.rn.f32x2 %0, %1, %2, %3;" : "=l"(d) : "l"(a), "l"(b), "l"(c)); return d;
}

__device__ __forceinline__ void cpy_sh(float* dst, const float* __restrict__ src, int n) {
    for (int k = threadIdx.x; k < n; k += NT) dst[k] = src[k];
}

// ---- generic layer: og = tid>>3 (32 groups), b = tid&7 ----
// TO in {1,2,4}. WS = weight row width. IS/OS = in/out strides.
template<int FI, int FO, int TO, int WS, int IS, int OS, bool CLIP, bool RESID>
__device__ __forceinline__ void layerG(const float* __restrict__ W,
                                       const float* __restrict__ bias,
                                       const float* __restrict__ in,
                                       float* __restrict__ out) {
    constexpr int OG = FO / TO;
    const int og = threadIdx.x >> 3;
    const int b  = threadIdx.x & 7;
    if (OG >= 32 || og < OG) {
        const int o0 = og * TO;
        const float* inp = in + b * IS;
        float acc1;
        ull acc2, acc4a, acc4b;
        if constexpr (TO == 1) acc1 = bias[o0];
        else if constexpr (TO == 2) {
            float2 bv = *(const float2*)(bias + o0);
            acc2 = pk2(bv.x, bv.y);
        } else {
            float4 bv = *(const float4*)(bias + o0);
            acc4a = pk2(bv.x, bv.y);
            acc4b = pk2(bv.z, bv.w);
        }
#pragma unroll
        for (int i4 = 0; i4 < FI / 4; ++i4) {
            float4 av = *(const float4*)(inp + 4 * i4);
            float ae[4] = {av.x, av.y, av.z, av.w};
#pragma unroll
            for (int e = 0; e < 4; ++e) {
                const int i = 4 * i4 + e;
                if constexpr (TO == 1) {
                    acc1 = fmaf(ae[e], W[i * WS + o0], acc1);
                } else if constexpr (TO == 2) {
                    acc2 = fma2(pk2(ae[e], ae[e]), *(const ull*)(W + i * WS + o0), acc2);
                } else {
                    ull aa = pk2(ae[e], ae[e]);
                    ulonglong2 wv = *(const ulonglong2*)(W + i * WS + o0);
                    acc4a = fma2(aa, wv.x, acc4a);
                    acc4b = fma2(aa, wv.y, acc4b);
                }
            }
        }
        float* op = out + b * OS + o0;
        if constexpr (TO == 1) {
            if constexpr (CLIP) acc1 = fminf(fmaxf(acc1, 0.0f), 6.0f);
            op[0] = acc1;
        } else if constexpr (TO == 2) {
            float r0, r1; upk2(acc2, r0, r1);
            if constexpr (CLIP) {
                r0 = fminf(fmaxf(r0, 0.0f), 6.0f);
                r1 = fminf(fmaxf(r1, 0.0f), 6.0f);
            }
            *(float2*)op = make_float2(r0, r1);
        } else {
            float r0, r1, r2, r3;
            upk2(acc4a, r0, r1); upk2(acc4b, r2, r3);
            if constexpr (CLIP) {
                r0 = fminf(fmaxf(r0, 0.0f), 6.0f);
                r1 = fminf(fmaxf(r1, 0.0f), 6.0f);
                r2 = fminf(fmaxf(r2, 0.0f), 6.0f);
                r3 = fminf(fmaxf(r3, 0.0f), 6.0f);
            }
            if constexpr (RESID) {
                float4 xv = *(const float4*)op;
                xv.x += r0; xv.y += r1; xv.z += r2; xv.w += r3;
                *(float4*)op = xv;
            } else {
                *(float4*)op = make_float4(r0, r1, r2, r3);
            }
        }
    }
}

// reward for current XS -> out[., t, 115]; one warp per item
__device__ __forceinline__ void reward(const float* __restrict__ sh,
                                       float* __restrict__ out,
                                       int b0, int t) {
    const int b = threadIdx.x >> 5;
    const int l = threadIdx.x & 31;
    float p0 = 0.f, p1 = 0.f, p2 = 0.f;
    const float* xr = sh + OXS + b * SXS;
    const float* Wr = sh + OWR;
    for (int i = l; i < STATE; i += 32) {
        float v = xr[i];
        p0 = fmaf(v, Wr[3 * i + 0], p0);
        p1 = fmaf(v, Wr[3 * i + 1], p1);
        p2 = fmaf(v, Wr[3 * i + 2], p2);
    }
#pragma unroll
    for (int off = 16; off > 0; off >>= 1) {
        p0 += __shfl_down_sync(0xffffffffu, p0, off);
        p1 += __shfl_down_sync(0xffffffffu, p1, off);
        p2 += __shfl_down_sync(0xffffffffu, p2, off);
    }
    if (l == 0) {
        p0 += sh[OBR + 0]; p1 += sh[OBR + 1]; p2 += sh[OBR + 2];
        out[((size_t)(b0 + b) * T_STEPS + t) * COUT + STATE] =
            -sqrtf(p0 * p0 + p1 * p1 + p2 * p2);
    }
}

__global__ void __launch_bounds__(NT, 2) worldnet_kernel(Params p) {
    extern __shared__ float sh[];
    const int tid = threadIdx.x;
    const int b0 = blockIdx.x * BT;
    const int og = tid >> 3;
    const int bb = tid & 7;

    // ---- one-time weight/bias staging ----
    for (int k = tid; k < 156 * 16; k += NT) {            // W0 padded, zero rows 115 & 155
        int r = k >> 4, c = k & 15;
        float v = 0.0f;
        if (r < 115)                  v = p.W[0][r * 16 + c];
        else if (r >= 116 && r < 155) v = p.W[0][(r - 1) * 16 + c];
        sh[OW0 + k] = v;
    }
    cpy_sh(sh + OW1, p.W[1], 16 * 32);
    cpy_sh(sh + OW2, p.W[2], 32 * 64);
    cpy_sh(sh + OW3, p.W[3], 64 * 128);
    cpy_sh(sh + OW4, p.W[4], 128 * 64);
    cpy_sh(sh + OW5, p.W[5], 64 * 32);
    cpy_sh(sh + OW6, p.W[6], 32 * 16);
    cpy_sh(sh + OW7, p.W[7], 16 * 8);
    for (int k = tid; k < 8 * 120; k += NT) {             // W8 padded [8][120]
        int i = k / 120, o = k - i * 120;
        sh[OW8 + k] = (o < STATE) ? p.W[8][i * STATE + o] : 0.0f;
    }
    for (int k = tid; k < 348; k += NT)
        sh[OWR + k] = (k < STATE * 3) ? p.Wr[k] : 0.0f;
    cpy_sh(sh + OB0, p.b[0], 16);
    cpy_sh(sh + OB1, p.b[1], 32);
    cpy_sh(sh + OB2, p.b[2], 64);
    cpy_sh(sh + OB3, p.b[3], 128);
    cpy_sh(sh + OB4, p.b[4], 64);
    cpy_sh(sh + OB5, p.b[5], 32);
    cpy_sh(sh + OB6, p.b[6], 16);
    cpy_sh(sh + OB7, p.b[7], 8);
    for (int k = tid; k < 120; k += NT)
        sh[OB8 + k] = (k < STATE) ? p.b[8][k] : 0.0f;
    for (int k = tid; k < 4; k += NT)
        sh[OBR + k] = (k < 3) ? p.br[k] : 0.0f;

    // ---- init x0 (col 115 zero pad) ----
    for (int k = tid; k < BT * SXS; k += NT) {
        int b = k / SXS, i = k - b * SXS;
        sh[OXS + k] = (i < STATE)
            ? p.u[(size_t)(b0 + b) * T_STEPS * CIN + i] : 0.0f;
    }
    __syncthreads();

    // ---- time loop ----
    for (int t = 0; t < T_STEPS; ++t) {
        // reward for previous step (XS = x_t, stable since L8 barrier)
        if (t > 0) reward(sh, p.out, b0, t - 1);
        // stage actions a_t into BUFB cols 24..63 (col 63 = pad zero)
        for (int k = tid; k < BT * 40; k += NT) {
            int b = k / 40, j = k - b * 40;
            sh[OBUFB + b * SBB + AOFF + j] = (j < ACT)
                ? p.u[((size_t)(b0 + b) * T_STEPS + t) * CIN + STATE + j] : 0.0f;
        }
        // out[:, t, 0:116] = x_t (col 115 = pad, overwritten by reward next top)
        for (int k = tid; k < BT * 29; k += NT) {
            int b = k / 29, c = k - b * 29;
            float4 v = *(const float4*)(sh + OXS + b * SXS + 4 * c);
            *(float4*)(p.out + ((size_t)(b0 + b) * T_STEPS + t) * COUT + 4 * c) = v;
        }
        __syncthreads();

        // ---- L0: concat(x,a)[156pad] -> 16, split FI in 2 halves (32 groups) ----
        {
            const int o = og & 15;
            const int h = og >> 4;
            float acc;
            if (h == 0) {
                acc = sh[OB0 + o];
                const float* xr = sh + OXS + bb * SXS;
#pragma unroll
                for (int i4 = 0; i4 < 19; ++i4) {            // rows 0..75
                    float4 av = *(const float4*)(xr + 4 * i4);
                    acc = fmaf(av.x, sh[OW0 + (4 * i4 + 0) * 16 + o], acc);
                    acc = fmaf(av.y, sh[OW0 + (4 * i4 + 1) * 16 + o], acc);
                    acc = fmaf(av.z, sh[OW0 + (4 * i4 + 2) * 16 + o], acc);
                    acc = fmaf(av.w, sh[OW0 + (4 * i4 + 3) * 16 + o], acc);
                }
            } else {
                acc = 0.0f;
                const float* xr = sh + OXS + bb * SXS;
#pragma unroll
                for (int i4 = 0; i4 < 10; ++i4) {            // rows 76..115 (115 = pad zero)
                    float4 av = *(const float4*)(xr + 76 + 4 * i4);
                    const int r = 76 + 4 * i4;
                    acc = fmaf(av.x, sh[OW0 + (r + 0) * 16 + o], acc);
                    acc = fmaf(av.y, sh[OW0 + (r + 1) * 16 + o], acc);
                    acc = fmaf(av.z, sh[OW0 + (r + 2) * 16 + o], acc);
                    acc = fmaf(av.w, sh[OW0 + (r + 3) * 16 + o], acc);
                }
                const float* ar = sh + OBUFB + bb * SBB + AOFF;
#pragma unroll
                for (int j4 = 0; j4 < 10; ++j4) {            // act rows 116..155 (155 = pad)
                    float4 av = *(const float4*)(ar + 4 * j4);
                    const int r = 116 + 4 * j4;
                    acc = fmaf(av.x, sh[OW0 + (r + 0) * 16 + o], acc);
                    acc = fmaf(av.y, sh[OW0 + (r + 1) * 16 + o], acc);
                    acc = fmaf(av.z, sh[OW0 + (r + 2) * 16 + o], acc);
                    acc = fmaf(av.w, sh[OW0 + (r + 3) * 16 + o], acc);
                }
                sh[OBUFA + bb * SBA + 32 + o] = acc;          // scratch in free BUFA cols
            }
            __syncthreads();
            if (h == 0) {
                acc += sh[OBUFA + bb * SBA + 32 + o];
                acc = fminf(fmaxf(acc, 0.0f), 6.0f);
                sh[OBUFB + bb * SBB + o] = acc;
            }
        }
        __syncthreads();

        //            FI   FO  TO  WS   IS   OS   CLIP  RESID
        layerG< 16,  32, 1,  32, SBB, SBA, true, false>(sh + OW1, sh + OB1, sh + OBUFB, sh + OBUFA); __syncthreads();
        layerG< 32,  64, 2,  64, SBA, SBB, true, false>(sh + OW2, sh + OB2, sh + OBUFA, sh + OBUFB); __syncthreads();
        layerG< 64, 128, 4, 128, SBB, SBA, true, false>(sh + OW3, sh + OB3, sh + OBUFB, sh + OBUFA); __syncthreads();
        layerG<128,  64, 2,  64, SBA, SBB, true, false>(sh + OW4, sh + OB4, sh + OBUFA, sh + OBUFB); __syncthreads();
        layerG< 64,  32, 1,  32, SBB, SBA, true, false>(sh + OW5, sh + OB5, sh + OBUFB, sh + OBUFA); __syncthreads();
        layerG< 32,  16, 1,  16, SBA, SBB, true, false>(sh + OW6, sh + OB6, sh + OBUFA, sh + OBUFB); __syncthreads();
        layerG< 16,   8, 1,   8, SBB, SBA, true, false>(sh + OW7, sh + OB7, sh + OBUFB, sh + OBUFA); __syncthreads();
        // L8 (8 -> 116, W padded to 120) fused with residual: XS += delta
        layerG<  8, 116, 4, 120, SBA, SXS, false, true>(sh + OW8, sh + OB8, sh + OBUFA, sh + OXS);  __syncthreads();
        // loop back: top segment computes reward(t) from updated XS
    }
    // trailing reward for t = 127
    reward(sh, p.out, b0, T_STEPS - 1);
}

extern "C" void kernel_launch(void* const* d_in, const int* in_sizes, int n_in,
                              void* d_out, int out_size) {
    Params p;
    p.u = (const float*)d_in[0];
    for (int i = 0; i < 9; ++i) {
        p.W[i] = (const float*)d_in[1 + 2 * i];
        p.b[i] = (const float*)d_in[2 + 2 * i];
    }
    p.Wr = (const float*)d_in[19];
    p.br = (const float*)d_in[20];
    p.out = (float*)d_out;

    cudaFuncSetAttribute(worldnet_kernel,
                         cudaFuncAttributeMaxDynamicSharedMemorySize, SMEM_BYTES);
    worldnet_kernel<<<2048 / BT, NT, SMEM_BYTES>>>(p);
}

// round 9
// speedup vs baseline: 1.4008x; 1.4008x over previous
#include <cuda_runtime.h>
#include <math.h>

typedef unsigned long long ull;

// ---------------- problem constants ----------------
#define NT       256     // 8 warps
#define BT       16      // batch items per block -> 128 blocks
#define T_STEPS  128
#define STATE    115
#define ACT      39
#define CIN      154
#define COUT     116

#define SBUF 132         // unified stride for BUFA/BUFB/XS
#define SA   44          // action stride

// ---------------- shared memory layout (float offsets) ----------------
#define OW0   0          // padded [156][16]
#define OW1   2496       // 16*32
#define OW2   3008       // 32*64
#define OW3   5056       // 64*128
#define OW4   13248      // 128*64
#define OW5   21440      // 64*32
#define OW6   23488      // 32*16
#define OW7   24000      // 16*8
#define OW8   24128      // padded [8][120]
#define OWR   25088      // 348
#define OB0   25436
#define OB1   25452
#define OB2   25484
#define OB3   25548
#define OB4   25676
#define OB5   25740
#define OB6   25772
#define OB7   25788
#define OB8   25796      // 120 padded
#define OBR   25916
#define OBUFA 25920      // 16*132 = 2112
#define OBUFB 28032      // 2112
#define OXS   30144      // 2112 (cols 115..131 zero-ish pads)
#define OAB   32256      // 16*44 (col 39 zero)
#define OSCR  32960      // 1024 floats (L0 combine scratch)
#define SMEM_FLOATS 33984
#define SMEM_BYTES  (SMEM_FLOATS * 4)   // 135936 B -> 1 CTA/SM

struct Params {
    const float* u;
    const float* W[9];
    const float* b[9];
    const float* Wr;
    const float* br;
    float* out;
};

// ---- packed f32x2 helpers ----
__device__ __forceinline__ ull pk2(float x, float y) {
    ull r; asm("mov.b64 %0, {%1, %2};" : "=l"(r) : "f"(x), "f"(y)); return r;
}
__device__ __forceinline__ void upk2(ull v, float& x, float& y) {
    asm("mov.b64 {%0, %1}, %2;" : "=f"(x), "=f"(y) : "l"(v));
}
__device__ __forceinline__ ull fma2(ull a, ull b, ull c) {
    ull d; asm("fma.rn.f32x2 %0, %1, %2, %3;" : "=l"(d) : "l"(a), "l"(b), "l"(c)); return d;
}

__device__ __forceinline__ void cpy_sh(float* dst, const float* __restrict__ src, int n) {
    for (int k = threadIdx.x; k < n; k += NT) dst[k] = src[k];
}

// ---- TB=2 layer: og = tid>>3, bp = tid&7; thread computes items bp and bp+8.
// Each weight loaded ONCE, applied to both items. TO in {2,4}.
template<int FI, int FO, int TO, int WS, bool CLIP, bool RESID>
__device__ __forceinline__ void layer2(const float* __restrict__ W,
                                       const float* __restrict__ bias,
                                       const float* __restrict__ in,
                                       float* __restrict__ out) {
    constexpr int OG = FO / TO;
    const int og = threadIdx.x >> 3;
    const int bp = threadIdx.x & 7;
    if (OG >= 32 || og < OG) {
        const int o0 = og * TO;
        const float* i0 = in + bp * SBUF;
        const float* i1 = in + (bp + 8) * SBUF;
        ull aA0, aB0, aA1, aB1;            // item0: A,B ; item1: A,B (B unused for TO=2)
        if constexpr (TO == 2) {
            float2 bv = *(const float2*)(bias + o0);
            aA0 = pk2(bv.x, bv.y); aA1 = aA0;
        } else {
            float4 bv = *(const float4*)(bias + o0);
            aA0 = pk2(bv.x, bv.y); aB0 = pk2(bv.z, bv.w);
            aA1 = aA0;             aB1 = aB0;
        }
#pragma unroll
        for (int i4 = 0; i4 < FI / 4; ++i4) {
            float4 v0 = *(const float4*)(i0 + 4 * i4);
            float4 v1 = *(const float4*)(i1 + 4 * i4);
            float e0[4] = {v0.x, v0.y, v0.z, v0.w};
            float e1[4] = {v1.x, v1.y, v1.z, v1.w};
#pragma unroll
            for (int e = 0; e < 4; ++e) {
                const int i = 4 * i4 + e;
                ull x0 = pk2(e0[e], e0[e]);
                ull x1 = pk2(e1[e], e1[e]);
                if constexpr (TO == 2) {
                    ull w = *(const ull*)(W + i * WS + o0);
                    aA0 = fma2(x0, w, aA0);
                    aA1 = fma2(x1, w, aA1);
                } else {
                    ulonglong2 w = *(const ulonglong2*)(W + i * WS + o0);
                    aA0 = fma2(x0, w.x, aA0); aB0 = fma2(x0, w.y, aB0);
                    aA1 = fma2(x1, w.x, aA1); aB1 = fma2(x1, w.y, aB1);
                }
            }
        }
        // write both items
#pragma unroll
        for (int it = 0; it < 2; ++it) {
            float* op = out + (bp + 8 * it) * SBUF + o0;
            ull pa = it ? aA1 : aA0;
            if constexpr (TO == 2) {
                float r0, r1; upk2(pa, r0, r1);
                if constexpr (CLIP) {
                    r0 = fminf(fmaxf(r0, 0.0f), 6.0f);
                    r1 = fminf(fmaxf(r1, 0.0f), 6.0f);
                }
                *(float2*)op = make_float2(r0, r1);
            } else {
                ull pb = it ? aB1 : aB0;
                float r0, r1, r2, r3;
                upk2(pa, r0, r1); upk2(pb, r2, r3);
                if constexpr (CLIP) {
                    r0 = fminf(fmaxf(r0, 0.0f), 6.0f);
                    r1 = fminf(fmaxf(r1, 0.0f), 6.0f);
                    r2 = fminf(fmaxf(r2, 0.0f), 6.0f);
                    r3 = fminf(fmaxf(r3, 0.0f), 6.0f);
                }
                if constexpr (RESID) {
                    float4 xv = *(const float4*)op;
                    xv.x += r0; xv.y += r1; xv.z += r2; xv.w += r3;
                    *(float4*)op = xv;
                } else {
                    *(float4*)op = make_float4(r0, r1, r2, r3);
                }
            }
        }
    }
}

// ---- TB=1 layer for tiny layers (L6, L7): og = tid>>4, b = tid&15, TO=2 ----
template<int FI, int FO, int WS, bool CLIP>
__device__ __forceinline__ void layer1(const float* __restrict__ W,
                                       const float* __restrict__ bias,
                                       const float* __restrict__ in,
                                       float* __restrict__ out) {
    constexpr int OG = FO / 2;
    const int og = threadIdx.x >> 4;
    const int b  = threadIdx.x & 15;
    if (og < OG) {
        const int o0 = og * 2;
        const float* inp = in + b * SBUF;
        float2 bv = *(const float2*)(bias + o0);
        ull acc = pk2(bv.x, bv.y);
#pragma unroll
        for (int i4 = 0; i4 < FI / 4; ++i4) {
            float4 av = *(const float4*)(inp + 4 * i4);
            float ae[4] = {av.x, av.y, av.z, av.w};
#pragma unroll
            for (int e = 0; e < 4; ++e)
                acc = fma2(pk2(ae[e], ae[e]),
                           *(const ull*)(W + (4 * i4 + e) * WS + o0), acc);
        }
        float r0, r1; upk2(acc, r0, r1);
        if constexpr (CLIP) {
            r0 = fminf(fmaxf(r0, 0.0f), 6.0f);
            r1 = fminf(fmaxf(r1, 0.0f), 6.0f);
        }
        *(float2*)(out + b * SBUF + o0) = make_float2(r0, r1);
    }
}

// ---- L0 partial: NF4 float4 rows for two items, shared weight loads ----
template<int NF4>
__device__ __forceinline__ void l0_part2(const float* __restrict__ s0,
                                         const float* __restrict__ s1,
                                         const float* __restrict__ W,
                                         ull& a0, ull& a1) {
#pragma unroll
    for (int i4 = 0; i4 < NF4; ++i4) {
        float4 v0 = *(const float4*)(s0 + 4 * i4);
        float4 v1 = *(const float4*)(s1 + 4 * i4);
        float e0[4] = {v0.x, v0.y, v0.z, v0.w};
        float e1[4] = {v1.x, v1.y, v1.z, v1.w};
#pragma unroll
        for (int e = 0; e < 4; ++e) {
            ull w = *(const ull*)(W + (4 * i4 + e) * 16);
            a0 = fma2(pk2(e0[e], e0[e]), w, a0);
            a1 = fma2(pk2(e1[e], e1[e]), w, a1);
        }
    }
}

__global__ void __launch_bounds__(NT, 1) worldnet_kernel(Params p) {
    extern __shared__ float sh[];
    const int tid = threadIdx.x;
    const int b0 = blockIdx.x * BT;
    const int og = tid >> 3;
    const int bp = tid & 7;

    // ---- one-time weight/bias staging ----
    for (int k = tid; k < 156 * 16; k += NT) {            // W0 padded, zero rows 115 & 155
        int r = k >> 4, c = k & 15;
        float v = 0.0f;
        if (r < 115)                  v = p.W[0][r * 16 + c];
        else if (r >= 116 && r < 155) v = p.W[0][(r - 1) * 16 + c];
        sh[OW0 + k] = v;
    }
    cpy_sh(sh + OW1, p.W[1], 16 * 32);
    cpy_sh(sh + OW2, p.W[2], 32 * 64);
    cpy_sh(sh + OW3, p.W[3], 64 * 128);
    cpy_sh(sh + OW4, p.W[4], 128 * 64);
    cpy_sh(sh + OW5, p.W[5], 64 * 32);
    cpy_sh(sh + OW6, p.W[6], 32 * 16);
    cpy_sh(sh + OW7, p.W[7], 16 * 8);
    for (int k = tid; k < 8 * 120; k += NT) {             // W8 padded [8][120]
        int i = k / 120, o = k - i * 120;
        sh[OW8 + k] = (o < STATE) ? p.W[8][i * STATE + o] : 0.0f;
    }
    for (int k = tid; k < 348; k += NT)
        sh[OWR + k] = (k < STATE * 3) ? p.Wr[k] : 0.0f;
    cpy_sh(sh + OB0, p.b[0], 16);
    cpy_sh(sh + OB1, p.b[1], 32);
    cpy_sh(sh + OB2, p.b[2], 64);
    cpy_sh(sh + OB3, p.b[3], 128);
    cpy_sh(sh + OB4, p.b[4], 64);
    cpy_sh(sh + OB5, p.b[5], 32);
    cpy_sh(sh + OB6, p.b[6], 16);
    cpy_sh(sh + OB7, p.b[7], 8);
    for (int k = tid; k < 120; k += NT)
        sh[OB8 + k] = (k < STATE) ? p.b[8][k] : 0.0f;
    for (int k = tid; k < 4; k += NT)
        sh[OBR + k] = (k < 3) ? p.br[k] : 0.0f;

    // ---- init XS (cols >= 115 zero), zero OAB pad col ----
    for (int k = tid; k < BT * SBUF; k += NT) {
        int b = k / SBUF, i = k - b * SBUF;
        sh[OXS + k] = (i < STATE)
            ? p.u[(size_t)(b0 + b) * T_STEPS * CIN + i] : 0.0f;
    }
    if (tid < BT) sh[OAB + tid * SA + ACT] = 0.0f;
    __syncthreads();

    // ---- time loop ----
    for (int t = 0; t < T_STEPS; ++t) {
        // stage actions a_t
        for (int k = tid; k < BT * ACT; k += NT) {
            int b = k / ACT, j = k - b * ACT;
            sh[OAB + b * SA + j] =
                p.u[((size_t)(b0 + b) * T_STEPS + t) * CIN + STATE + j];
        }
        // out[:, t, 0:116] = x_t (col 115 overwritten by reward below)
        for (int k = tid; k < BT * 29; k += NT) {
            int b = k / 29, c = k - b * 29;
            float4 v = *(const float4*)(sh + OXS + b * SBUF + 4 * c);
            *(float4*)(p.out + ((size_t)(b0 + b) * T_STEPS + t) * COUT + 4 * c) = v;
        }
        __syncthreads();

        // ---- L0: 156pad -> 16. 8 pairs x 4 K-quarters, TB=2 -> 256 threads ----
        {
            const int pg = og & 7;
            const int q  = og >> 3;
            const int o0 = pg * 2;
            ull a0, a1;
            if (q == 0) {
                float2 bv = *(const float2*)(sh + OB0 + o0);
                a0 = pk2(bv.x, bv.y); a1 = a0;
            } else { a0 = 0ull; a1 = 0ull; }
            const float* x0 = sh + OXS + bp * SBUF;
            const float* x1 = sh + OXS + (bp + 8) * SBUF;
            if (q == 0)      l0_part2<10>(x0,      x1,      sh + OW0 + o0,           a0, a1);
            else if (q == 1) l0_part2<10>(x0 + 40, x1 + 40, sh + OW0 + 40 * 16 + o0, a0, a1);
            else if (q == 2) l0_part2< 9>(x0 + 80, x1 + 80, sh + OW0 + 80 * 16 + o0, a0, a1);
            else             l0_part2<10>(sh + OAB + bp * SA, sh + OAB + (bp + 8) * SA,
                                          sh + OW0 + 116 * 16 + o0, a0, a1);
            *(ull*)(sh + OSCR + ((pg * 16 + bp) * 4 + q) * 2)       = a0;
            *(ull*)(sh + OSCR + ((pg * 16 + bp + 8) * 4 + q) * 2)   = a1;
        }
        __syncthreads();
        if (tid < 128) {  // combine quarters, clip, write OBUFB
            const int pg = tid >> 4, it = tid & 15;
            const float* base = sh + OSCR + (pg * 16 + it) * 8;
            ulonglong2 v01 = *(const ulonglong2*)(base);
            ulonglong2 v23 = *(const ulonglong2*)(base + 4);
            float a0, a1, c0, c1, d0, d1, e0, e1;
            upk2(v01.x, a0, a1); upk2(v01.y, c0, c1);
            upk2(v23.x, d0, d1); upk2(v23.y, e0, e1);
            float lo = (a0 + c0) + (d0 + e0);
            float hi = (a1 + c1) + (d1 + e1);
            lo = fminf(fmaxf(lo, 0.0f), 6.0f);
            hi = fminf(fmaxf(hi, 0.0f), 6.0f);
            *(float2*)(sh + OBUFB + it * SBUF + pg * 2) = make_float2(lo, hi);
        }
        __syncthreads();

        //            FI   FO  TO  WS    CLIP  RESID
        layer2< 16,  32, 2,  32, true, false>(sh + OW1, sh + OB1, sh + OBUFB, sh + OBUFA); __syncthreads();
        layer2< 32,  64, 4,  64, true, false>(sh + OW2, sh + OB2, sh + OBUFA, sh + OBUFB); __syncthreads();
        layer2< 64, 128, 4, 128, true, false>(sh + OW3, sh + OB3, sh + OBUFB, sh + OBUFA); __syncthreads();
        layer2<128,  64, 4,  64, true, false>(sh + OW4, sh + OB4, sh + OBUFA, sh + OBUFB); __syncthreads();
        layer2< 64,  32, 2,  32, true, false>(sh + OW5, sh + OB5, sh + OBUFB, sh + OBUFA); __syncthreads();
        layer1< 32,  16,  16, true>(sh + OW6, sh + OB6, sh + OBUFA, sh + OBUFB); __syncthreads();
        layer1< 16,   8,   8, true>(sh + OW7, sh + OB7, sh + OBUFB, sh + OBUFA); __syncthreads();
        // L8: 8 -> 120 (116 real), fused residual into XS
        layer2<  8, 120, 4, 120, false, true>(sh + OW8, sh + OB8, sh + OBUFA, sh + OXS);  __syncthreads();

        // ---- reward from x_{t+1}: 16 lanes per item ----
        {
            int b = tid >> 4;
            int l = tid & 15;
            float p0 = 0.f, p1 = 0.f, p2 = 0.f;
            const float* xr = sh + OXS + b * SBUF;
            const float* Wr = sh + OWR;
#pragma unroll
            for (int i = l; i < STATE; i += 16) {
                float v = xr[i];
                p0 = fmaf(v, Wr[3 * i + 0], p0);
                p1 = fmaf(v, Wr[3 * i + 1], p1);
                p2 = fmaf(v, Wr[3 * i + 2], p2);
            }
#pragma unroll
            for (int off = 8; off > 0; off >>= 1) {
                p0 += __shfl_down_sync(0xffffffffu, p0, off, 16);
                p1 += __shfl_down_sync(0xffffffffu, p1, off, 16);
                p2 += __shfl_down_sync(0xffffffffu, p2, off, 16);
            }
            if (l == 0) {
                p0 += sh[OBR + 0]; p1 += sh[OBR + 1]; p2 += sh[OBR + 2];
                p.out[((size_t)(b0 + b) * T_STEPS + t) * COUT + STATE] =
                    -sqrtf(p0 * p0 + p1 * p1 + p2 * p2);
            }
        }
        // no barrier: next-iter top writes OAB/gmem, reads OXS — safe vs reward
    }
}

extern "C" void kernel_launch(void* const* d_in, const int* in_sizes, int n_in,
                              void* d_out, int out_size) {
    Params p;
    p.u = (const float*)d_in[0];
    for (int i = 0; i < 9; ++i) {
        p.W[i] = (const float*)d_in[1 + 2 * i];
        p.b[i] = (const float*)d_in[2 + 2 * i];
    }
    p.Wr = (const float*)d_in[19];
    p.br = (const float*)d_in[20];
    p.out = (float*)d_out;

    cudaFuncSetAttribute(worldnet_kernel,
                         cudaFuncAttributeMaxDynamicSharedMemorySize, SMEM_BYTES);
    worldnet_kernel<<<2048 / BT, NT, SMEM_BYTES>>>(p);
}

// round 10
// speedup vs baseline: 1.4331x; 1.0230x over previous
#include <cuda_runtime.h>
#include <math.h>

typedef unsigned long long ull;

// ---------------- problem constants ----------------
#define NT       256     // 8 warps; two independent 128-thread groups
#define BT       16      // batch items per block -> 128 blocks
#define T_STEPS  128
#define STATE    115
#define ACT      39
#define CIN      154
#define COUT     116

#define SBUF 132
#define SA   44

// ---------------- shared memory layout (float offsets) ----------------
#define OW0   0          // padded [156][16]
#define OW1   2496
#define OW2   3008
#define OW3   5056
#define OW4   13248
#define OW5   21440
#define OW6   23488
#define OW7   24000
#define OW8   24128      // padded [8][120]
#define OWR   25088      // 348
#define OB0   25436
#define OB1   25452
#define OB2   25484
#define OB3   25548
#define OB4   25676
#define OB5   25740
#define OB6   25772
#define OB7   25788
#define OB8   25796      // 120 padded
#define OBR   25916
#define OBUFA 25920      // 16*132
#define OBUFB 28032      // 16*132
#define OXS   30144      // 16*132 (cols >=115 zero)
#define OAB0  32256      // 16*44 (col 39 zero)
#define OAB1  32960      // 16*44
#define OSCR  33664      // 1024 floats
#define SMEM_FLOATS 34688
#define SMEM_BYTES  (SMEM_FLOATS * 4)   // 138752 B -> 1 CTA/SM

// group-scoped named barrier (ids 1 and 2)
#define GBAR() asm volatile("bar.sync %0, 128;" :: "r"(grp + 1) : "memory")

struct Params {
    const float* u;
    const float* W[9];
    const float* b[9];
    const float* Wr;
    const float* br;
    float* out;
};

// ---- packed f32x2 helpers ----
__device__ __forceinline__ ull pk2(float x, float y) {
    ull r; asm("mov.b64 %0, {%1, %2};" : "=l"(r) : "f"(x), "f"(y)); return r;
}
__device__ __forceinline__ void upk2(ull v, float& x, float& y) {
    asm("mov.b64 {%0, %1}, %2;" : "=f"(x), "=f"(y) : "l"(v));
}
__device__ __forceinline__ ull fma2(ull a, ull b, ull c) {
    ull d; asm("fma.rn.f32x2 %0, %1, %2, %3;" : "=l"(d) : "l"(a), "l"(b), "l"(c)); return d;
}

__device__ __forceinline__ void cpy_sh(float* dst, const float* __restrict__ src, int n) {
    for (int k = threadIdx.x; k < n; k += NT) dst[k] = src[k];
}

// ---- TB=2 layer inside one group: thread handles items (bp, bp+4) of the
// group's 8 items. in/out are group-base pointers. Weights broadcast in warp.
template<int FI, int FO, int TO, int WS, bool CLIP, bool RESID>
__device__ __forceinline__ void layerN(const float* __restrict__ W,
                                       const float* __restrict__ bias,
                                       const float* __restrict__ in,
                                       float* __restrict__ out,
                                       int og, int bp) {
    constexpr int OG = FO / TO;
    if (og < OG) {
        const int o0 = og * TO;
        const float* i0 = in + bp * SBUF;
        const float* i1 = in + (bp + 4) * SBUF;
        ull aA0, aB0, aA1, aB1;
        if constexpr (TO == 2) {
            float2 bv = *(const float2*)(bias + o0);
            aA0 = pk2(bv.x, bv.y); aA1 = aA0;
        } else {
            float4 bv = *(const float4*)(bias + o0);
            aA0 = pk2(bv.x, bv.y); aB0 = pk2(bv.z, bv.w);
            aA1 = aA0;             aB1 = aB0;
        }
#pragma unroll
        for (int i4 = 0; i4 < FI / 4; ++i4) {
            float4 v0 = *(const float4*)(i0 + 4 * i4);
            float4 v1 = *(const float4*)(i1 + 4 * i4);
            float e0[4] = {v0.x, v0.y, v0.z, v0.w};
            float e1[4] = {v1.x, v1.y, v1.z, v1.w};
#pragma unroll
            for (int e = 0; e < 4; ++e) {
                const int i = 4 * i4 + e;
                ull x0 = pk2(e0[e], e0[e]);
                ull x1 = pk2(e1[e], e1[e]);
                if constexpr (TO == 2) {
                    ull w = *(const ull*)(W + i * WS + o0);
                    aA0 = fma2(x0, w, aA0);
                    aA1 = fma2(x1, w, aA1);
                } else {
                    ulonglong2 w = *(const ulonglong2*)(W + i * WS + o0);
                    aA0 = fma2(x0, w.x, aA0); aB0 = fma2(x0, w.y, aB0);
                    aA1 = fma2(x1, w.x, aA1); aB1 = fma2(x1, w.y, aB1);
                }
            }
        }
#pragma unroll
        for (int it = 0; it < 2; ++it) {
            float* op = out + (bp + 4 * it) * SBUF + o0;
            ull pa = it ? aA1 : aA0;
            if constexpr (TO == 2) {
                float r0, r1; upk2(pa, r0, r1);
                if constexpr (CLIP) {
                    r0 = fminf(fmaxf(r0, 0.0f), 6.0f);
                    r1 = fminf(fmaxf(r1, 0.0f), 6.0f);
                }
                *(float2*)op = make_float2(r0, r1);
            } else {
                ull pb = it ? aB1 : aB0;
                float r0, r1, r2, r3;
                upk2(pa, r0, r1); upk2(pb, r2, r3);
                if constexpr (CLIP) {
                    r0 = fminf(fmaxf(r0, 0.0f), 6.0f);
                    r1 = fminf(fmaxf(r1, 0.0f), 6.0f);
                    r2 = fminf(fmaxf(r2, 0.0f), 6.0f);
                    r3 = fminf(fmaxf(r3, 0.0f), 6.0f);
                }
                if constexpr (RESID) {
                    float4 xv = *(const float4*)op;
                    xv.x += r0; xv.y += r1; xv.z += r2; xv.w += r3;
                    *(float4*)op = xv;
                } else {
                    *(float4*)op = make_float4(r0, r1, r2, r3);
                }
            }
        }
    }
}

// ---- L0 partial: NF4 float4 rows for two items, shared weight loads ----
template<int NF4>
__device__ __forceinline__ void l0_part2(const float* __restrict__ s0,
                                         const float* __restrict__ s1,
                                         const float* __restrict__ W,
                                         ull& a0, ull& a1) {
#pragma unroll
    for (int i4 = 0; i4 < NF4; ++i4) {
        float4 v0 = *(const float4*)(s0 + 4 * i4);
        float4 v1 = *(const float4*)(s1 + 4 * i4);
        float e0[4] = {v0.x, v0.y, v0.z, v0.w};
        float e1[4] = {v1.x, v1.y, v1.z, v1.w};
#pragma unroll
        for (int e = 0; e < 4; ++e) {
            ull w = *(const ull*)(W + (4 * i4 + e) * 16);
            a0 = fma2(pk2(e0[e], e0[e]), w, a0);
            a1 = fma2(pk2(e1[e], e1[e]), w, a1);
        }
    }
}

// reward for x stored in XS (= x_{t+1} when called after L8): 16 lanes/item
__device__ __forceinline__ void reward16(const float* __restrict__ sh,
                                         float* __restrict__ out,
                                         int b0, int itemBase, int gtid, int t) {
    const int it = itemBase + (gtid >> 4);
    const int l = gtid & 15;
    float p0 = 0.f, p1 = 0.f, p2 = 0.f;
    const float* xr = sh + OXS + it * SBUF;
    const float* Wr = sh + OWR;
#pragma unroll
    for (int i = l; i < STATE; i += 16) {
        float v = xr[i];
        p0 = fmaf(v, Wr[3 * i + 0], p0);
        p1 = fmaf(v, Wr[3 * i + 1], p1);
        p2 = fmaf(v, Wr[3 * i + 2], p2);
    }
#pragma unroll
    for (int off = 8; off > 0; off >>= 1) {
        p0 += __shfl_down_sync(0xffffffffu, p0, off, 16);
        p1 += __shfl_down_sync(0xffffffffu, p1, off, 16);
        p2 += __shfl_down_sync(0xffffffffu, p2, off, 16);
    }
    if (l == 0) {
        p0 += sh[OBR + 0]; p1 += sh[OBR + 1]; p2 += sh[OBR + 2];
        out[((size_t)(b0 + it) * T_STEPS + t) * COUT + STATE] =
            -sqrtf(p0 * p0 + p1 * p1 + p2 * p2);
    }
}

__global__ void __launch_bounds__(NT, 1) worldnet_kernel(Params p) {
    extern __shared__ float sh[];
    const int tid = threadIdx.x;
    const int grp = tid >> 7;       // 0 or 1
    const int gtid = tid & 127;
    const int og = gtid >> 2;       // 0..31
    const int bp = gtid & 3;        // 0..3
    const int b0 = blockIdx.x * BT;
    const int itemBase = grp * 8;

    // ---- one-time weight/bias staging (all 256 threads) ----
    for (int k = tid; k < 156 * 16; k += NT) {
        int r = k >> 4, c = k & 15;
        float v = 0.0f;
        if (r < 115)                  v = p.W[0][r * 16 + c];
        else if (r >= 116 && r < 155) v = p.W[0][(r - 1) * 16 + c];
        sh[OW0 + k] = v;
    }
    cpy_sh(sh + OW1, p.W[1], 16 * 32);
    cpy_sh(sh + OW2, p.W[2], 32 * 64);
    cpy_sh(sh + OW3, p.W[3], 64 * 128);
    cpy_sh(sh + OW4, p.W[4], 128 * 64);
    cpy_sh(sh + OW5, p.W[5], 64 * 32);
    cpy_sh(sh + OW6, p.W[6], 32 * 16);
    cpy_sh(sh + OW7, p.W[7], 16 * 8);
    for (int k = tid; k < 8 * 120; k += NT) {
        int i = k / 120, o = k - i * 120;
        sh[OW8 + k] = (o < STATE) ? p.W[8][i * STATE + o] : 0.0f;
    }
    for (int k = tid; k < 348; k += NT)
        sh[OWR + k] = (k < STATE * 3) ? p.Wr[k] : 0.0f;
    cpy_sh(sh + OB0, p.b[0], 16);
    cpy_sh(sh + OB1, p.b[1], 32);
    cpy_sh(sh + OB2, p.b[2], 64);
    cpy_sh(sh + OB3, p.b[3], 128);
    cpy_sh(sh + OB4, p.b[4], 64);
    cpy_sh(sh + OB5, p.b[5], 32);
    cpy_sh(sh + OB6, p.b[6], 16);
    cpy_sh(sh + OB7, p.b[7], 8);
    for (int k = tid; k < 120; k += NT)
        sh[OB8 + k] = (k < STATE) ? p.b[8][k] : 0.0f;
    for (int k = tid; k < 4; k += NT)
        sh[OBR + k] = (k < 3) ? p.br[k] : 0.0f;

    // ---- init XS (cols >= 115 zero) ----
    for (int k = tid; k < BT * SBUF; k += NT) {
        int b = k / SBUF, i = k - b * SBUF;
        sh[OXS + k] = (i < STATE)
            ? p.u[(size_t)(b0 + b) * T_STEPS * CIN + i] : 0.0f;
    }
    // actions for t=0 into OAB0; zero pad col 39 of both buffers
    for (int k = tid; k < BT * ACT; k += NT) {
        int b = k / ACT, j = k - b * ACT;
        sh[OAB0 + b * SA + j] = p.u[(size_t)(b0 + b) * T_STEPS * CIN + STATE + j];
    }
    if (tid < 2 * BT) {
        int buf = tid >> 4, b = tid & 15;
        sh[(buf ? OAB1 : OAB0) + b * SA + ACT] = 0.0f;
        sh[(buf ? OAB1 : OAB0) + b * SA + ACT + 1] = 0.0f;
        sh[(buf ? OAB1 : OAB0) + b * SA + ACT + 2] = 0.0f;
        sh[(buf ? OAB1 : OAB0) + b * SA + ACT + 3] = 0.0f;
        sh[(buf ? OAB1 : OAB0) + b * SA + ACT + 4] = 0.0f;
    }
    __syncthreads();
    // after this point the two groups never share a barrier

    const float* bufAG = sh + OBUFA + itemBase * SBUF;
    float* bufAGw = sh + OBUFA + itemBase * SBUF;
    float* bufBGw = sh + OBUFB + itemBase * SBUF;
    float* xsGw   = sh + OXS   + itemBase * SBUF;

    // ---- time loop (group-independent) ----
    for (int t = 0; t < T_STEPS; ++t) {
        // reward for previous step (XS = x_t since this group's L8 barrier)
        if (t > 0) reward16(sh, p.out, b0, itemBase, gtid, t - 1);
        // out[:, t, 0:116] = x_t
        {
            const int it = itemBase + (gtid >> 4);
            for (int c = gtid & 15; c < 29; c += 16) {
                float4 v = *(const float4*)(sh + OXS + it * SBUF + 4 * c);
                *(float4*)(p.out + ((size_t)(b0 + it) * T_STEPS + t) * COUT + 4 * c) = v;
            }
        }
        // prefetch actions for t+1 into the other buffer
        if (t < T_STEPS - 1) {
            const int it = itemBase + (gtid >> 4);
            float* ab = sh + (((t + 1) & 1) ? OAB1 : OAB0) + it * SA;
            const float* us = p.u + ((size_t)(b0 + it) * T_STEPS + t + 1) * CIN + STATE;
            for (int j = gtid & 15; j < ACT; j += 16) ab[j] = us[j];
        }
        // ---- L0 partial: 8 output-pairs x 4 K-quarters ----
        {
            const int pg = og & 7;
            const int q  = og >> 3;
            const int o0 = pg * 2;
            ull a0, a1;
            if (q == 0) {
                float2 bv = *(const float2*)(sh + OB0 + o0);
                a0 = pk2(bv.x, bv.y); a1 = a0;
            } else { a0 = 0ull; a1 = 0ull; }
            const int i0 = itemBase + bp, i1 = i0 + 4;
            const float* x0 = sh + OXS + i0 * SBUF;
            const float* x1 = sh + OXS + i1 * SBUF;
            const float* abase = sh + ((t & 1) ? OAB1 : OAB0);
            if (q == 0)      l0_part2<10>(x0,      x1,      sh + OW0 + o0,           a0, a1);
            else if (q == 1) l0_part2<10>(x0 + 40, x1 + 40, sh + OW0 + 40 * 16 + o0, a0, a1);
            else if (q == 2) l0_part2< 9>(x0 + 80, x1 + 80, sh + OW0 + 80 * 16 + o0, a0, a1);
            else             l0_part2<10>(abase + i0 * SA, abase + i1 * SA,
                                          sh + OW0 + 116 * 16 + o0, a0, a1);
            *(ull*)(sh + OSCR + (i0 * 8 + pg) * 8 + q * 2) = a0;
            *(ull*)(sh + OSCR + (i1 * 8 + pg) * 8 + q * 2) = a1;
        }
        GBAR();
        if (gtid < 64) {   // combine quarters -> OBUFB
            const int pg = gtid & 7;
            const int it = itemBase + (gtid >> 3);
            const float* base = sh + OSCR + (it * 8 + pg) * 8;
            ulonglong2 v01 = *(const ulonglong2*)(base);
            ulonglong2 v23 = *(const ulonglong2*)(base + 4);
            float a0, a1, c0, c1, d0, d1, e0, e1;
            upk2(v01.x, a0, a1); upk2(v01.y, c0, c1);
            upk2(v23.x, d0, d1); upk2(v23.y, e0, e1);
            float lo = (a0 + c0) + (d0 + e0);
            float hi = (a1 + c1) + (d1 + e1);
            lo = fminf(fmaxf(lo, 0.0f), 6.0f);
            hi = fminf(fmaxf(hi, 0.0f), 6.0f);
            *(float2*)(sh + OBUFB + it * SBUF + pg * 2) = make_float2(lo, hi);
        }
        GBAR();

        //            FI   FO  TO  WS    CLIP  RESID
        layerN< 16,  32, 2,  32, true, false>(sh + OW1, sh + OB1, bufBGw, bufAGw, og, bp); GBAR();
        layerN< 32,  64, 4,  64, true, false>(sh + OW2, sh + OB2, bufAG,  bufBGw, og, bp); GBAR();
        layerN< 64, 128, 4, 128, true, false>(sh + OW3, sh + OB3, bufBGw, bufAGw, og, bp); GBAR();
        layerN<128,  64, 4,  64, true, false>(sh + OW4, sh + OB4, bufAG,  bufBGw, og, bp); GBAR();
        layerN< 64,  32, 2,  32, true, false>(sh + OW5, sh + OB5, bufBGw, bufAGw, og, bp); GBAR();
        layerN< 32,  16, 2,  16, true, false>(sh + OW6, sh + OB6, bufAG,  bufBGw, og, bp); GBAR();
        layerN< 16,   8, 2,   8, true, false>(sh + OW7, sh + OB7, bufBGw, bufAGw, og, bp); GBAR();
        layerN<  8, 120, 4, 120, false, true>(sh + OW8, sh + OB8, bufAG,  xsGw,  og, bp); GBAR();
        // loop back: top segment (reward/store/prefetch/L0) needs no extra barrier
    }
    // trailing reward for t = 127
    reward16(sh, p.out, b0, itemBase, gtid, T_STEPS - 1);
}

extern "C" void kernel_launch(void* const* d_in, const int* in_sizes, int n_in,
                              void* d_out, int out_size) {
    Params p;
    p.u = (const float*)d_in[0];
    for (int i = 0; i < 9; ++i) {
        p.W[i] = (const float*)d_in[1 + 2 * i];
        p.b[i] = (const float*)d_in[2 + 2 * i];
    }
    p.Wr = (const float*)d_in[19];
    p.br = (const float*)d_in[20];
    p.out = (float*)d_out;

    cudaFuncSetAttribute(worldnet_kernel,
                         cudaFuncAttributeMaxDynamicSharedMemorySize, SMEM_BYTES);
    worldnet_kernel<<<2048 / BT, NT, SMEM_BYTES>>>(p);
}